// round 8
// baseline (speedup 1.0000x reference)
#include <cuda_runtime.h>
#include <cstdint>

// Problem dims
#define G1 512
#define E_EDGES 16384
#define S1 8192
#define S2 8192
#define BT 128

typedef unsigned long long ull;

// -------- device scratch --------
__device__ int g_cnt[G1];
__device__ int g_cur[G1];
__device__ int g_offsets[G1 + 1];
__device__ int g_edge_list[E_EDGES];        // packed: (t1 << 16) | e
__device__ float g_xperm[256 * S1];         // 8MB: x, tf32-rounded, K-cols permuted per 16-block

// -------- x preprocess (vectorized) + counter zeroing --------
// col' = (c%4)*4 + c/4 : one output float4 group g = original cols {g, g+4, g+8, g+12}
__global__ __launch_bounds__(256) void xperm_kernel(const float* __restrict__ x) {
    if (blockIdx.x == 0) {           // fold counter zeroing into this launch
        g_cnt[threadIdx.x] = 0;
        g_cnt[threadIdx.x + 256] = 0;
    }
    const size_t blk = (size_t)blockIdx.x * 256 + threadIdx.x;   // one 16-float block
    const float4* src = reinterpret_cast<const float4*>(x + blk * 16);
    float4 a = __ldg(src + 0), b = __ldg(src + 1), c = __ldg(src + 2), d = __ldg(src + 3);
    float v[16] = {a.x,a.y,a.z,a.w, b.x,b.y,b.z,b.w, c.x,c.y,c.z,c.w, d.x,d.y,d.z,d.w};
    uint32_t t[16];
    #pragma unroll
    for (int i = 0; i < 16; i++)
        asm("cvt.rna.tf32.f32 %0, %1;" : "=r"(t[i]) : "f"(v[i]));
    float4* dst = reinterpret_cast<float4*>(g_xperm + blk * 16);
    #pragma unroll
    for (int g = 0; g < 4; g++)
        dst[g] = make_float4(__uint_as_float(t[g]),     __uint_as_float(t[g + 4]),
                             __uint_as_float(t[g + 8]), __uint_as_float(t[g + 12]));
}

// -------- multi-CTA bucketing --------
__global__ __launch_bounds__(1024) void hist_kernel(const int* __restrict__ ei) {
    const int e = blockIdx.x * 1024 + threadIdx.x;
    atomicAdd(&g_cnt[ei[e]], 1);
}

__global__ __launch_bounds__(512) void scan_kernel() {
    __shared__ int s[G1];
    const int t = threadIdx.x;
    const int c = g_cnt[t];
    s[t] = c;
    __syncthreads();
    #pragma unroll
    for (int d = 1; d < G1; d <<= 1) {
        int v = (t >= d) ? s[t - d] : 0;
        __syncthreads();
        s[t] += v;
        __syncthreads();
    }
    g_offsets[t + 1] = s[t];
    if (t == 0) g_offsets[0] = 0;
    g_cur[t] = s[t] - c;
}

__global__ __launch_bounds__(1024) void scatter_kernel(const int* __restrict__ ei) {
    const int e = blockIdx.x * 1024 + threadIdx.x;
    const int t0 = ei[e];
    const int t1 = ei[E_EDGES + e];
    const int pos = atomicAdd(&g_cur[t0], 1);
    g_edge_list[pos] = (t1 << 16) | e;
}

// -------- helpers --------
__device__ __forceinline__ void cp16(uint32_t d, const void* g) {
    asm volatile("cp.async.cg.shared.global [%0], [%1], 16;" :: "r"(d), "l"(g));
}
__device__ __forceinline__ void cp_commit() { asm volatile("cp.async.commit_group;"); }
__device__ __forceinline__ void cp_wait1()  { asm volatile("cp.async.wait_group 1;"); }

__device__ __forceinline__ float tf32f(float f) {
    uint32_t t;
    asm("cvt.rna.tf32.f32 %0, %1;" : "=r"(t) : "f"(f));
    return __uint_as_float(t);
}
__device__ __forceinline__ void mma8(float* c,
                                     uint32_t a0, uint32_t a1, uint32_t a2, uint32_t a3,
                                     uint32_t b0, uint32_t b1) {
    asm volatile(
        "mma.sync.aligned.m16n8k8.row.col.f32.tf32.tf32.f32 "
        "{%0,%1,%2,%3}, {%4,%5,%6,%7}, {%8,%9}, {%0,%1,%2,%3};"
        : "+f"(c[0]), "+f"(c[1]), "+f"(c[2]), "+f"(c[3])
        : "r"(a0), "r"(a1), "r"(a2), "r"(a3), "r"(b0), "r"(b1));
}

union F4U { float4 f; uint32_t u[4]; };

// -------- main tensor SpMM: 2 edges (K=32) per iteration --------
// grid (512 t0, 2 batch halves), 128 threads = 4 warps; warp w owns batch rows 32w..32w+31.
__global__ __launch_bounds__(128) void spmm_mma(
    const float* __restrict__ values,
    const float* __restrict__ bias,
    float* __restrict__ out)
{
    // x slots: 128 rows x 128B (2 edges x 16 permuted cols), XOR-swizzled by (row&7)<<4
    __shared__ __align__(16) unsigned char xsm[2][128 * 128];   // 32 KB
    __shared__ __align__(16) float vt[2][2][16][16];             //  4 KB

    const int tid  = threadIdx.x;
    const int wid  = tid >> 5;
    const int lane = tid & 31;
    const int gid  = lane >> 2;
    const int tig  = lane & 3;
    const int t0    = blockIdx.x;
    const int bbase = blockIdx.y * BT;

    float acc[2][2][4];
    #pragma unroll
    for (int a = 0; a < 2; a++)
        #pragma unroll
        for (int b = 0; b < 2; b++)
            #pragma unroll
            for (int q = 0; q < 4; q++) acc[a][b][q] = 0.0f;

    // v staging coords (thread stages 2 elems per edge)
    const int vi = tid >> 3;
    const int vj = (tid & 7) << 1;
    const int kp = ((vi & 3) << 2) + (vi >> 2);
    const int vcol = kp ^ (((vj >> 1) & 3) << 2);

    uint32_t xbase[2];
    xbase[0] = (uint32_t)__cvta_generic_to_shared(xsm[0]) + (uint32_t)tid * 128u;
    xbase[1] = (uint32_t)__cvta_generic_to_shared(xsm[1]) + (uint32_t)tid * 128u;
    const uint32_t key = (uint32_t)(tid & 7) << 4;

    const int beg = g_offsets[t0];
    const int n   = g_offsets[t0 + 1] - beg;
    const int P   = (n + 1) >> 1;

    if (P > 0) {
        float2 vA, vB;
        // ---- prologue: describe + stage pair 0 into slot 0 ----
        {
            const int pA = g_edge_list[beg];
            const int eA = pA & 0xFFFF, t1a = pA >> 16;
            int eB = eA, t1b = t1a;
            const bool hB = (n > 1);
            if (hB) { const int pB = g_edge_list[beg + 1]; eB = pB & 0xFFFF; t1b = pB >> 16; }
            vA = __ldg(reinterpret_cast<const float2*>(values + ((size_t)eA << 8)) + tid);
            vB = hB ? __ldg(reinterpret_cast<const float2*>(values + ((size_t)eB << 8)) + tid)
                    : make_float2(0.f, 0.f);
            const float* sA = g_xperm + (size_t)(bbase + tid) * S1 + t1a * 16;
            const float* sB = g_xperm + (size_t)(bbase + tid) * S1 + t1b * 16;
            #pragma unroll
            for (int g = 0; g < 4; g++) cp16(xbase[0] + ((g * 16) ^ key), sA + g * 4);
            #pragma unroll
            for (int g = 0; g < 4; g++) cp16(xbase[0] + ((64 + g * 16) ^ key), sB + g * 4);
            cp_commit();
        }

        const int bcol = (tig << 2) ^ (((gid >> 1) & 3) << 2);
        const int r0 = (wid << 5) + gid;
        const int r1 = r0 + 16;

        for (int k = 0; k < P; k++) {
            const int c = k & 1;

            __syncthreads();   // (A) compute on slot c (prev use) & vt[c] finished everywhere

            // STS current pair's v into vt[c]
            vt[c][0][vj][vcol]     = tf32f(vA.x);
            vt[c][0][vj + 1][vcol] = tf32f(vA.y);
            vt[c][1][vj][vcol]     = tf32f(vB.x);
            vt[c][1][vj + 1][vcol] = tf32f(vB.y);

            // stage pair k+1 into x slot c^1; prefetch its v into regs
            if (k + 1 < P) {
                const int i0 = beg + 2 * (k + 1);
                const int pA = g_edge_list[i0];
                const int eA = pA & 0xFFFF, t1a = pA >> 16;
                int eB = eA, t1b = t1a;
                const bool hB = (i0 + 1 < beg + n);
                if (hB) { const int pB = g_edge_list[i0 + 1]; eB = pB & 0xFFFF; t1b = pB >> 16; }
                const float* sA = g_xperm + (size_t)(bbase + tid) * S1 + t1a * 16;
                const float* sB = g_xperm + (size_t)(bbase + tid) * S1 + t1b * 16;
                #pragma unroll
                for (int g = 0; g < 4; g++) cp16(xbase[c ^ 1] + ((g * 16) ^ key), sA + g * 4);
                #pragma unroll
                for (int g = 0; g < 4; g++) cp16(xbase[c ^ 1] + ((64 + g * 16) ^ key), sB + g * 4);
                vA = __ldg(reinterpret_cast<const float2*>(values + ((size_t)eA << 8)) + tid);
                vB = hB ? __ldg(reinterpret_cast<const float2*>(values + ((size_t)eB << 8)) + tid)
                        : make_float2(0.f, 0.f);
            }
            cp_commit();       // empty commit keeps group counting aligned
            cp_wait1();        // pair k's x arrived

            __syncthreads();   // (B) slot c x-data + vt[c] visible CTA-wide

            // ---- compute both edges of pair k ----
            const unsigned char* xc = xsm[c];
            #pragma unroll
            for (int ep = 0; ep < 2; ep++) {
                F4U aL0, aH0, aL1, aH1, b0, b1;
                const uint32_t off = (uint32_t)(ep * 64 + tig * 16);
                aL0.f = *reinterpret_cast<const float4*>(xc + (r0     ) * 128 + (off ^ (((r0     ) & 7) << 4)));
                aH0.f = *reinterpret_cast<const float4*>(xc + (r0 +  8) * 128 + (off ^ (((r0 +  8) & 7) << 4)));
                aL1.f = *reinterpret_cast<const float4*>(xc + (r1     ) * 128 + (off ^ (((r1     ) & 7) << 4)));
                aH1.f = *reinterpret_cast<const float4*>(xc + (r1 +  8) * 128 + (off ^ (((r1 +  8) & 7) << 4)));
                b0.f  = *reinterpret_cast<const float4*>(&vt[c][ep][gid    ][bcol]);
                b1.f  = *reinterpret_cast<const float4*>(&vt[c][ep][gid + 8][bcol]);

                mma8(acc[0][0], aL0.u[0], aH0.u[0], aL0.u[1], aH0.u[1], b0.u[0], b0.u[1]);
                mma8(acc[0][0], aL0.u[2], aH0.u[2], aL0.u[3], aH0.u[3], b0.u[2], b0.u[3]);
                mma8(acc[0][1], aL0.u[0], aH0.u[0], aL0.u[1], aH0.u[1], b1.u[0], b1.u[1]);
                mma8(acc[0][1], aL0.u[2], aH0.u[2], aL0.u[3], aH0.u[3], b1.u[2], b1.u[3]);
                mma8(acc[1][0], aL1.u[0], aH1.u[0], aL1.u[1], aH1.u[1], b0.u[0], b0.u[1]);
                mma8(acc[1][0], aL1.u[2], aH1.u[2], aL1.u[3], aH1.u[3], b0.u[2], b0.u[3]);
                mma8(acc[1][1], aL1.u[0], aH1.u[0], aL1.u[1], aH1.u[1], b1.u[0], b1.u[1]);
                mma8(acc[1][1], aL1.u[2], aH1.u[2], aL1.u[3], aH1.u[3], b1.u[2], b1.u[3]);
            }
        }
    }

    // ---- epilogue: bias + float2 stores (n == 0 -> pure bias) ----
    #pragma unroll
    for (int t = 0; t < 2; t++) {
        const int row = bbase + (wid << 5) + (t << 4) + gid;
        #pragma unroll
        for (int nt = 0; nt < 2; nt++) {
            const int col = t0 * 16 + (nt << 3) + (tig << 1);
            const float2 bv = __ldg(reinterpret_cast<const float2*>(bias + col));
            float2 o0 = make_float2(acc[t][nt][0] + bv.x, acc[t][nt][1] + bv.y);
            float2 o1 = make_float2(acc[t][nt][2] + bv.x, acc[t][nt][3] + bv.y);
            *reinterpret_cast<float2*>(out + (size_t)row * S2 + col)       = o0;
            *reinterpret_cast<float2*>(out + (size_t)(row + 8) * S2 + col) = o1;
        }
    }
}

// -------- launch --------
extern "C" void kernel_launch(void* const* d_in, const int* in_sizes, int n_in,
                              void* d_out, int out_size) {
    const float* x      = (const float*)d_in[0];   // (256, 8192)
    const float* values = (const float*)d_in[1];   // (4194304,)
    const float* bias   = (const float*)d_in[2];   // (8192,)
    const int*   eidx   = (const int*)d_in[3];     // (2, 16384)
    float* out = (float*)d_out;                    // (256, 8192)

    xperm_kernel<<<(256 * S1 / 16) / 256, 256>>>(x);   // also zeroes g_cnt
    hist_kernel<<<E_EDGES / 1024, 1024>>>(eidx);
    scan_kernel<<<1, 512>>>();
    scatter_kernel<<<E_EDGES / 1024, 1024>>>(eidx);
    dim3 grid(G1, 2);
    spmm_mma<<<grid, 128>>>(values, bias, out);
}

// round 9
// speedup vs baseline: 1.0347x; 1.0347x over previous
#include <cuda_runtime.h>
#include <cstdint>

// Problem dims
#define G1 512
#define E_EDGES 16384
#define S1 8192
#define S2 8192
#define BT 128

// -------- device scratch --------
__device__ int g_cnt[G1];
__device__ int g_cur[G1];
__device__ int g_offsets[G1 + 1];
__device__ int g_edge_list[E_EDGES];        // packed: (t1 << 16) | e
__device__ float g_xperm[256 * S1];         // 8MB: x, tf32-rounded, K-cols permuted per 16-block

// -------- x preprocess (vectorized) + counter zeroing --------
// col' = (c%4)*4 + c/4 : output float4 group g holds original cols {g, g+4, g+8, g+12}
__global__ __launch_bounds__(256) void xperm_kernel(const float* __restrict__ x) {
    if (blockIdx.x == 0) {
        g_cnt[threadIdx.x] = 0;
        g_cnt[threadIdx.x + 256] = 0;
    }
    const size_t blk = (size_t)blockIdx.x * 256 + threadIdx.x;
    const float4* src = reinterpret_cast<const float4*>(x + blk * 16);
    float4 a = __ldg(src + 0), b = __ldg(src + 1), c = __ldg(src + 2), d = __ldg(src + 3);
    float v[16] = {a.x,a.y,a.z,a.w, b.x,b.y,b.z,b.w, c.x,c.y,c.z,c.w, d.x,d.y,d.z,d.w};
    uint32_t t[16];
    #pragma unroll
    for (int i = 0; i < 16; i++)
        asm("cvt.rna.tf32.f32 %0, %1;" : "=r"(t[i]) : "f"(v[i]));
    float4* dst = reinterpret_cast<float4*>(g_xperm + blk * 16);
    #pragma unroll
    for (int g = 0; g < 4; g++)
        dst[g] = make_float4(__uint_as_float(t[g]),     __uint_as_float(t[g + 4]),
                             __uint_as_float(t[g + 8]), __uint_as_float(t[g + 12]));
}

// -------- multi-CTA bucketing --------
__global__ __launch_bounds__(1024) void hist_kernel(const int* __restrict__ ei) {
    const int e = blockIdx.x * 1024 + threadIdx.x;
    atomicAdd(&g_cnt[ei[e]], 1);
}

__global__ __launch_bounds__(512) void scan_kernel() {
    __shared__ int s[G1];
    const int t = threadIdx.x;
    const int c = g_cnt[t];
    s[t] = c;
    __syncthreads();
    #pragma unroll
    for (int d = 1; d < G1; d <<= 1) {
        int v = (t >= d) ? s[t - d] : 0;
        __syncthreads();
        s[t] += v;
        __syncthreads();
    }
    g_offsets[t + 1] = s[t];
    if (t == 0) g_offsets[0] = 0;
    g_cur[t] = s[t] - c;
}

__global__ __launch_bounds__(1024) void scatter_kernel(const int* __restrict__ ei) {
    const int e = blockIdx.x * 1024 + threadIdx.x;
    const int t0 = ei[e];
    const int t1 = ei[E_EDGES + e];
    const int pos = atomicAdd(&g_cur[t0], 1);
    g_edge_list[pos] = (t1 << 16) | e;
}

// -------- helpers --------
__device__ __forceinline__ uint32_t tf32u(float f) {
    uint32_t t;
    asm("cvt.rna.tf32.f32 %0, %1;" : "=r"(t) : "f"(f));
    return t;
}
__device__ __forceinline__ void mma8(float* c,
                                     uint32_t a0, uint32_t a1, uint32_t a2, uint32_t a3,
                                     uint32_t b0, uint32_t b1) {
    asm volatile(
        "mma.sync.aligned.m16n8k8.row.col.f32.tf32.tf32.f32 "
        "{%0,%1,%2,%3}, {%4,%5,%6,%7}, {%8,%9}, {%0,%1,%2,%3};"
        : "+f"(c[0]), "+f"(c[1]), "+f"(c[2]), "+f"(c[3])
        : "r"(a0), "r"(a1), "r"(a2), "r"(a3), "r"(b0), "r"(b1));
}

union F4U { float4 f; uint32_t u[4]; };

// -------- main tensor SpMM: warp-autonomous, NO smem, NO barriers --------
// grid (512 t0, 2 batch halves), 128 threads = 4 warps; warp w owns batch rows 32w..32w+31.
// Per lane per edge: 4x LDG.128 (A fragments, permuted x) + 8x LDG.32 (B fragments, v).
__global__ __launch_bounds__(128) void spmm_mma(
    const float* __restrict__ values,
    const float* __restrict__ bias,
    float* __restrict__ out)
{
    const int tid  = threadIdx.x;
    const int lane = tid & 31;
    const int wid  = tid >> 5;
    const int gid  = lane >> 2;
    const int tig  = lane & 3;
    const int t0    = blockIdx.x;
    const int bbase = blockIdx.y * BT;

    // this lane's A source rows: (bbase + 32*wid + gid) + {0, 8, 16, 24}
    const float* xrow = g_xperm + (size_t)(bbase + (wid << 5) + gid) * S1 + (tig << 2);

    float acc[2][2][4];
    #pragma unroll
    for (int a = 0; a < 2; a++)
        #pragma unroll
        for (int b = 0; b < 2; b++)
            #pragma unroll
            for (int q = 0; q < 4; q++) acc[a][b][q] = 0.0f;

    const int beg = g_offsets[t0];
    const int end = g_offsets[t0 + 1];

    F4U  xf[2][4];     // 2-slot pipeline of A fragments
    float vb[2][8];    // 2-slot pipeline of B fragments (fp32, cvt at consume)

    // issue loads for edge index k into slot s (no-op if k >= end)
    auto issue = [&](int k, int s) {
        if (k < end) {
            const int p  = g_edge_list[k];
            const int e  = p & 0xFFFF;
            const int t1 = p >> 16;
            const float* xp = xrow + t1 * 16;
            xf[s][0].f = __ldg(reinterpret_cast<const float4*>(xp));
            xf[s][1].f = __ldg(reinterpret_cast<const float4*>(xp +  8 * S1));
            xf[s][2].f = __ldg(reinterpret_cast<const float4*>(xp + 16 * S1));
            xf[s][3].f = __ldg(reinterpret_cast<const float4*>(xp + 24 * S1));
            const float* vp = values + ((size_t)e << 8) + (tig << 4) + gid;
            #pragma unroll
            for (int m = 0; m < 4; m++) {
                vb[s][m]     = __ldg(vp + m * 64);      // j = gid
                vb[s][4 + m] = __ldg(vp + m * 64 + 8);  // j = gid + 8
            }
        }
    };

    issue(beg, 0);
    issue(beg + 1, 1);

    for (int k = beg; k < end; k++) {
        const int s = (k - beg) & 1;

        // ---- consume slot s ----
        uint32_t b[8];
        #pragma unroll
        for (int i = 0; i < 8; i++) b[i] = tf32u(vb[s][i]);
        F4U X0 = xf[s][0], X1 = xf[s][1], X2 = xf[s][2], X3 = xf[s][3];

        // ---- issue edge k+2 into slot s (after regs consumed into locals) ----
        issue(k + 2, s);

        mma8(acc[0][0], X0.u[0], X1.u[0], X0.u[1], X1.u[1], b[0], b[1]);
        mma8(acc[0][0], X0.u[2], X1.u[2], X0.u[3], X1.u[3], b[2], b[3]);
        mma8(acc[0][1], X0.u[0], X1.u[0], X0.u[1], X1.u[1], b[4], b[5]);
        mma8(acc[0][1], X0.u[2], X1.u[2], X0.u[3], X1.u[3], b[6], b[7]);
        mma8(acc[1][0], X2.u[0], X3.u[0], X2.u[1], X3.u[1], b[0], b[1]);
        mma8(acc[1][0], X2.u[2], X3.u[2], X2.u[3], X3.u[3], b[2], b[3]);
        mma8(acc[1][1], X2.u[0], X3.u[0], X2.u[1], X3.u[1], b[4], b[5]);
        mma8(acc[1][1], X2.u[2], X3.u[2], X2.u[3], X3.u[3], b[6], b[7]);
    }

    // ---- epilogue: bias + float2 stores (n == 0 -> pure bias) ----
    #pragma unroll
    for (int t = 0; t < 2; t++) {
        const int row = bbase + (wid << 5) + (t << 4) + gid;
        #pragma unroll
        for (int nt = 0; nt < 2; nt++) {
            const int col = t0 * 16 + (nt << 3) + (tig << 1);
            const float2 bv = __ldg(reinterpret_cast<const float2*>(bias + col));
            float2 o0 = make_float2(acc[t][nt][0] + bv.x, acc[t][nt][1] + bv.y);
            float2 o1 = make_float2(acc[t][nt][2] + bv.x, acc[t][nt][3] + bv.y);
            *reinterpret_cast<float2*>(out + (size_t)row * S2 + col)       = o0;
            *reinterpret_cast<float2*>(out + (size_t)(row + 8) * S2 + col) = o1;
        }
    }
}

// -------- launch --------
extern "C" void kernel_launch(void* const* d_in, const int* in_sizes, int n_in,
                              void* d_out, int out_size) {
    const float* x      = (const float*)d_in[0];   // (256, 8192)
    const float* values = (const float*)d_in[1];   // (4194304,)
    const float* bias   = (const float*)d_in[2];   // (8192,)
    const int*   eidx   = (const int*)d_in[3];     // (2, 16384)
    float* out = (float*)d_out;                    // (256, 8192)

    xperm_kernel<<<(256 * S1 / 16) / 256, 256>>>(x);   // also zeroes g_cnt
    hist_kernel<<<E_EDGES / 1024, 1024>>>(eidx);
    scan_kernel<<<1, 512>>>();
    scatter_kernel<<<E_EDGES / 1024, 1024>>>(eidx);
    dim3 grid(G1, 2);
    spmm_mma<<<grid, 128>>>(values, bias, out);
}

// round 10
// speedup vs baseline: 2.0602x; 1.9911x over previous
#include <cuda_runtime.h>
#include <cstdint>

// Problem dims
#define G1 512
#define E_EDGES 16384
#define S1 8192
#define S2 8192
#define BT 128
#define MAXE 256   // per-t0 edge capacity (lambda=32, ~39 sigma headroom)

// -------- device scratch --------
__device__ float g_xperm[256 * S1];   // 8MB: x, tf32-rounded, K-cols permuted per 16-block

// -------- x preprocess (vectorized) --------
// col' = (c%4)*4 + c/4 : output float4 group g holds original cols {g, g+4, g+8, g+12}
__global__ __launch_bounds__(256) void xperm_kernel(const float* __restrict__ x) {
    const size_t blk = (size_t)blockIdx.x * 256 + threadIdx.x;
    const float4* src = reinterpret_cast<const float4*>(x + blk * 16);
    float4 a = __ldg(src + 0), b = __ldg(src + 1), c = __ldg(src + 2), d = __ldg(src + 3);
    float v[16] = {a.x,a.y,a.z,a.w, b.x,b.y,b.z,b.w, c.x,c.y,c.z,c.w, d.x,d.y,d.z,d.w};
    uint32_t t[16];
    #pragma unroll
    for (int i = 0; i < 16; i++)
        asm("cvt.rna.tf32.f32 %0, %1;" : "=r"(t[i]) : "f"(v[i]));
    float4* dst = reinterpret_cast<float4*>(g_xperm + blk * 16);
    #pragma unroll
    for (int g = 0; g < 4; g++)
        dst[g] = make_float4(__uint_as_float(t[g]),     __uint_as_float(t[g + 4]),
                             __uint_as_float(t[g + 8]), __uint_as_float(t[g + 12]));
}

// -------- helpers --------
__device__ __forceinline__ uint32_t tf32u(float f) {
    uint32_t t;
    asm("cvt.rna.tf32.f32 %0, %1;" : "=r"(t) : "f"(f));
    return t;
}
__device__ __forceinline__ void mma8(float* c,
                                     uint32_t a0, uint32_t a1, uint32_t a2, uint32_t a3,
                                     uint32_t b0, uint32_t b1) {
    asm volatile(
        "mma.sync.aligned.m16n8k8.row.col.f32.tf32.tf32.f32 "
        "{%0,%1,%2,%3}, {%4,%5,%6,%7}, {%8,%9}, {%0,%1,%2,%3};"
        : "+f"(c[0]), "+f"(c[1]), "+f"(c[2]), "+f"(c[3])
        : "r"(a0), "r"(a1), "r"(a2), "r"(a3), "r"(b0), "r"(b1));
}

union F4U { float4 f; uint32_t u[4]; };

// -------- main tensor SpMM: self-bucketing + warp-autonomous register pipeline --------
// grid (512 t0, 2 batch halves), 128 threads = 4 warps; warp w owns batch rows 32w..32w+31.
__global__ __launch_bounds__(128) void spmm_mma(
    const float* __restrict__ values,
    const float* __restrict__ bias,
    const int*   __restrict__ ei,
    float* __restrict__ out)
{
    __shared__ int s_list[MAXE];   // packed: (t1 << 16) | e
    __shared__ int s_cnt;

    const int tid  = threadIdx.x;
    const int lane = tid & 31;
    const int wid  = tid >> 5;
    const int gid  = lane >> 2;
    const int tig  = lane & 3;
    const int t0    = blockIdx.x;
    const int bbase = blockIdx.y * BT;

    // ---- self-bucket: scan edge_index for matches on t0 ----
    if (tid == 0) s_cnt = 0;
    __syncthreads();
    {
        const int4* ei4 = reinterpret_cast<const int4*>(ei);
        #pragma unroll 4
        for (int i = tid; i < E_EDGES / 4; i += 128) {
            const int4 q = __ldg(&ei4[i]);
            const int base = i << 2;
            if (q.x == t0) { int p = atomicAdd(&s_cnt, 1); if (p < MAXE) s_list[p] = (__ldg(ei + E_EDGES + base    ) << 16) | (base    ); }
            if (q.y == t0) { int p = atomicAdd(&s_cnt, 1); if (p < MAXE) s_list[p] = (__ldg(ei + E_EDGES + base + 1) << 16) | (base + 1); }
            if (q.z == t0) { int p = atomicAdd(&s_cnt, 1); if (p < MAXE) s_list[p] = (__ldg(ei + E_EDGES + base + 2) << 16) | (base + 2); }
            if (q.w == t0) { int p = atomicAdd(&s_cnt, 1); if (p < MAXE) s_list[p] = (__ldg(ei + E_EDGES + base + 3) << 16) | (base + 3); }
        }
    }
    __syncthreads();
    int n = s_cnt;
    if (n > MAXE) n = MAXE;

    // this lane's A source rows: (bbase + 32*wid + gid) + {0, 8, 16, 24}
    const float* xrow = g_xperm + (size_t)(bbase + (wid << 5) + gid) * S1 + (tig << 2);

    float acc[2][2][4];
    #pragma unroll
    for (int a = 0; a < 2; a++)
        #pragma unroll
        for (int b = 0; b < 2; b++)
            #pragma unroll
            for (int q = 0; q < 4; q++) acc[a][b][q] = 0.0f;

    F4U  xf[2][4];     // 2-slot pipeline of A fragments
    float vb[2][8];    // 2-slot pipeline of B fragments

    auto issue = [&](int k, int s) {
        if (k < n) {
            const int p  = s_list[k];                 // LDS: fast edge decode
            const int e  = p & 0xFFFF;
            const int t1 = p >> 16;
            const float* xp = xrow + t1 * 16;
            xf[s][0].f = __ldg(reinterpret_cast<const float4*>(xp));
            xf[s][1].f = __ldg(reinterpret_cast<const float4*>(xp +  8 * S1));
            xf[s][2].f = __ldg(reinterpret_cast<const float4*>(xp + 16 * S1));
            xf[s][3].f = __ldg(reinterpret_cast<const float4*>(xp + 24 * S1));
            const float* vp = values + ((size_t)e << 8) + (tig << 4) + gid;
            #pragma unroll
            for (int m = 0; m < 4; m++) {
                vb[s][m]     = __ldg(vp + m * 64);      // j = gid
                vb[s][4 + m] = __ldg(vp + m * 64 + 8);  // j = gid + 8
            }
        }
    };

    issue(0, 0);
    issue(1, 1);

    for (int k = 0; k < n; k++) {
        const int s = k & 1;

        uint32_t b[8];
        #pragma unroll
        for (int i = 0; i < 8; i++) b[i] = tf32u(vb[s][i]);
        F4U X0 = xf[s][0], X1 = xf[s][1], X2 = xf[s][2], X3 = xf[s][3];

        issue(k + 2, s);

        mma8(acc[0][0], X0.u[0], X1.u[0], X0.u[1], X1.u[1], b[0], b[1]);
        mma8(acc[0][0], X0.u[2], X1.u[2], X0.u[3], X1.u[3], b[2], b[3]);
        mma8(acc[0][1], X0.u[0], X1.u[0], X0.u[1], X1.u[1], b[4], b[5]);
        mma8(acc[0][1], X0.u[2], X1.u[2], X0.u[3], X1.u[3], b[6], b[7]);
        mma8(acc[1][0], X2.u[0], X3.u[0], X2.u[1], X3.u[1], b[0], b[1]);
        mma8(acc[1][0], X2.u[2], X3.u[2], X2.u[3], X3.u[3], b[2], b[3]);
        mma8(acc[1][1], X2.u[0], X3.u[0], X2.u[1], X3.u[1], b[4], b[5]);
        mma8(acc[1][1], X2.u[2], X3.u[2], X2.u[3], X3.u[3], b[6], b[7]);
    }

    // ---- epilogue: bias + float2 stores (n == 0 -> pure bias) ----
    #pragma unroll
    for (int t = 0; t < 2; t++) {
        const int row = bbase + (wid << 5) + (t << 4) + gid;
        #pragma unroll
        for (int nt = 0; nt < 2; nt++) {
            const int col = t0 * 16 + (nt << 3) + (tig << 1);
            const float2 bv = __ldg(reinterpret_cast<const float2*>(bias + col));
            float2 o0 = make_float2(acc[t][nt][0] + bv.x, acc[t][nt][1] + bv.y);
            float2 o1 = make_float2(acc[t][nt][2] + bv.x, acc[t][nt][3] + bv.y);
            *reinterpret_cast<float2*>(out + (size_t)row * S2 + col)       = o0;
            *reinterpret_cast<float2*>(out + (size_t)(row + 8) * S2 + col) = o1;
        }
    }
}

// -------- launch: exactly 2 kernels --------
extern "C" void kernel_launch(void* const* d_in, const int* in_sizes, int n_in,
                              void* d_out, int out_size) {
    const float* x      = (const float*)d_in[0];   // (256, 8192)
    const float* values = (const float*)d_in[1];   // (4194304,)
    const float* bias   = (const float*)d_in[2];   // (8192,)
    const int*   eidx   = (const int*)d_in[3];     // (2, 16384)
    float* out = (float*)d_out;                    // (256, 8192)

    xperm_kernel<<<(256 * S1 / 16) / 256, 256>>>(x);
    dim3 grid(G1, 2);
    spmm_mma<<<grid, 128>>>(values, bias, eidx, out);
}